// round 13
// baseline (speedup 1.0000x reference)
#include <cuda_runtime.h>
#include <cuda_fp16.h>
#include <cuda_bf16.h>
#include <mma.h>
#include <cstdint>

using namespace nvcuda;

#define N_NODES 131072
#define P_NODES 4096
#define B_GR    32
#define E_EDGES 2097152
#define IN_DIM  64
#define HID     128
#define OUT_DIM 16
#define CAP     64
#define EPSV    1e-5f
#define SLOPE   0.01f

// ---------------- scratch (device globals; no allocations allowed) ----------
__device__ int    g_deg_src[N_NODES];
__device__ int    g_cursor[N_NODES];                 // dst degree after build
__device__ int2   g_csre[(size_t)N_NODES * CAP];     // packed {src, raw ew}
__device__ __nv_bfloat16 g_x16[(size_t)N_NODES * IN_DIM];   // bf16 features * rs_src
__device__ __nv_bfloat16 g_w1t[HID * IN_DIM];        // W1^T  [n][k]
__device__ __nv_bfloat16 g_w2t[HID * HID];           // W2^T  [n][k]
__device__ __half g_h1pre[(size_t)N_NODES * HID];    // pre-norm h1 (fp16)
__device__ __half g_h1h[(size_t)N_NODES * HID];      // normalized h1 * rs_src (fp16)
__device__ __half g_h2pre[(size_t)N_NODES * HID];    // pre-norm h2 (fp16)
__device__ float  g_stats1[2 * HID];
__device__ float  g_stats2[2 * HID];
__device__ float  g_r[B_GR * 2 * HID];

// ---------------- setup -----------------------------------------------------

__global__ void k_zero() {
    int i = blockIdx.x * blockDim.x + threadIdx.x;
    if (i < N_NODES) { g_deg_src[i] = 0; g_cursor[i] = 0; }
    if (i < 2 * HID) { g_stats1[i] = 0.f; g_stats2[i] = 0.f; }
    if (i < B_GR * 2 * HID) { g_r[i] = 0.f; }
}

// 4 edges/thread: vector loads + independent atomic chains; writes packed CSR.
__global__ __launch_bounds__(256) void k_build(const int* __restrict__ src,
                                               const int* __restrict__ dst,
                                               const float* __restrict__ ew) {
    int e4 = (blockIdx.x * 256 + threadIdx.x) * 4;
    int4   s4 = *(const int4*)&src[e4];
    int4   d4 = *(const int4*)&dst[e4];
    float4 w4 = *(const float4*)&ew[e4];
    int p0 = atomicAdd(&g_cursor[d4.x], 1);
    int p1 = atomicAdd(&g_cursor[d4.y], 1);
    int p2 = atomicAdd(&g_cursor[d4.z], 1);
    int p3 = atomicAdd(&g_cursor[d4.w], 1);
    atomicAdd(&g_deg_src[s4.x], 1);
    atomicAdd(&g_deg_src[s4.y], 1);
    atomicAdd(&g_deg_src[s4.z], 1);
    atomicAdd(&g_deg_src[s4.w], 1);
    if (p0 < CAP) g_csre[(size_t)d4.x * CAP + p0] = make_int2(s4.x, __float_as_int(w4.x));
    if (p1 < CAP) g_csre[(size_t)d4.y * CAP + p1] = make_int2(s4.y, __float_as_int(w4.y));
    if (p2 < CAP) g_csre[(size_t)d4.z * CAP + p2] = make_int2(s4.z, __float_as_int(w4.z));
    if (p3 < CAP) g_csre[(size_t)d4.w * CAP + p3] = make_int2(s4.w, __float_as_int(w4.w));
}

// blocks [0,4096): features -> bf16 * rsqrt(deg_src); 8 floats/thread.
// block 4096: transpose W1,W2 to bf16 K-major.
__global__ __launch_bounds__(256) void k_prep(const float* __restrict__ x,
                                              const float* __restrict__ W1,
                                              const float* __restrict__ W2) {
    int b = blockIdx.x, t = threadIdx.x;
    if (b < 4096) {
        int i0 = b * 2048 + t * 8;
        int row = i0 >> 6;
        float rs = rsqrtf((float)max(g_deg_src[row], 1));
        float4 a = *(const float4*)&x[i0];
        float4 c = *(const float4*)&x[i0 + 4];
        uint4 o;
        __nv_bfloat162 b0 = __floats2bfloat162_rn(a.x * rs, a.y * rs);
        __nv_bfloat162 b1 = __floats2bfloat162_rn(a.z * rs, a.w * rs);
        __nv_bfloat162 b2 = __floats2bfloat162_rn(c.x * rs, c.y * rs);
        __nv_bfloat162 b3 = __floats2bfloat162_rn(c.z * rs, c.w * rs);
        o.x = *(uint32_t*)&b0; o.y = *(uint32_t*)&b1;
        o.z = *(uint32_t*)&b2; o.w = *(uint32_t*)&b3;
        *(uint4*)&g_x16[i0] = o;
    } else {
        for (int i = t; i < HID * IN_DIM; i += 256) {
            int n = i / IN_DIM, k = i % IN_DIM;
            g_w1t[i] = __float2bfloat16(W1[k * HID + n]);
        }
        for (int i = t; i < HID * HID; i += 256) {
            int n = i / HID, k = i % HID;
            g_w2t[i] = __float2bfloat16(W2[k * HID + n]);
        }
    }
}

// ---------------- fused gather + WMMA GEMM + GraphNorm stats -----------------
// CTA owns 128 nodes. 8 warps: warp w gathers nodes [w*16, w*16+16) into the
// smem A tile (MLP=8 inner loop), then block does the 128xK @ K^T x128 GEMM.
__global__ __launch_bounds__(256) void k_gemm(int layer) {
    extern __shared__ __nv_bfloat16 smb[];
    const int K   = (layer == 1) ? IN_DIM : HID;
    const int pitch = K + 8;
    __nv_bfloat16* sA = smb;                       // [128][pitch]
    __nv_bfloat16* sB = smb + 128 * pitch;         // [128][pitch]
    const __nv_bfloat16* Bg = (layer == 1) ? g_w1t : g_w2t;
    int tid = threadIdx.x, w = tid >> 5, lane = tid & 31;
    size_t m0 = (size_t)blockIdx.x * 128;

    // weight tile load (async w.r.t. gather below; completes before sync)
    int vecs = K / 8;
    for (int i = tid; i < 128 * vecs; i += 256) {
        int r = i / vecs, c = i % vecs;
        *(uint4*)&sB[r * pitch + c * 8] = *(const uint4*)&Bg[(size_t)r * K + c * 8];
    }

    // gather 16 nodes per warp directly into sA
    for (int nn = 0; nn < 16; nn++) {
        int v = (int)m0 + w * 16 + nn;
        int degf = g_cursor[v];
        int deg  = min(degf, CAP);
        const int2* ce = &g_csre[(size_t)v * CAP];
        if (layer == 1) {
            float a0 = 0.f, a1 = 0.f;
            for (int i = 0; i < deg; i += 8) {
                int   idx[8];
                float wt[8];
                #pragma unroll
                for (int u = 0; u < 8; u++) {
                    int j = min(i + u, deg - 1);
                    int2 e = __ldg(&ce[j]);
                    idx[u] = e.x;
                    wt[u]  = (i + u < deg) ? __int_as_float(e.y) : 0.f;
                }
                float2 vv[8];
                #pragma unroll
                for (int u = 0; u < 8; u++)
                    vv[u] = __bfloat1622float2(((const __nv_bfloat162*)(g_x16 + (size_t)idx[u] * IN_DIM))[lane]);
                #pragma unroll
                for (int u = 0; u < 8; u++) {
                    a0 += wt[u] * vv[u].x;
                    a1 += wt[u] * vv[u].y;
                }
            }
            float rd = rsqrtf((float)max(degf, 1));
            ((__nv_bfloat162*)&sA[(w * 16 + nn) * pitch])[lane] =
                __floats2bfloat162_rn(a0 * rd, a1 * rd);
        } else {
            float a0 = 0.f, a1 = 0.f, a2 = 0.f, a3 = 0.f;
            for (int i = 0; i < deg; i += 8) {
                int   idx[8];
                float wt[8];
                #pragma unroll
                for (int u = 0; u < 8; u++) {
                    int j = min(i + u, deg - 1);
                    int2 e = __ldg(&ce[j]);
                    idx[u] = e.x;
                    wt[u]  = (i + u < deg) ? __int_as_float(e.y) : 0.f;
                }
                uint2 uu[8];
                #pragma unroll
                for (int u = 0; u < 8; u++)
                    uu[u] = ((const uint2*)(g_h1h + (size_t)idx[u] * HID))[lane];
                #pragma unroll
                for (int u = 0; u < 8; u++) {
                    float2 p = __half22float2(*(const __half2*)&uu[u].x);
                    float2 q = __half22float2(*(const __half2*)&uu[u].y);
                    a0 += wt[u] * p.x; a1 += wt[u] * p.y;
                    a2 += wt[u] * q.x; a3 += wt[u] * q.y;
                }
            }
            float rd = rsqrtf((float)max(degf, 1));
            __nv_bfloat162 b0 = __floats2bfloat162_rn(a0 * rd, a1 * rd);
            __nv_bfloat162 b1 = __floats2bfloat162_rn(a2 * rd, a3 * rd);
            uint2 packed;
            packed.x = *(uint32_t*)&b0;
            packed.y = *(uint32_t*)&b1;
            *(uint2*)&sA[(w * 16 + nn) * pitch + 4 * lane] = packed;
        }
    }
    __syncthreads();

    wmma::fragment<wmma::accumulator, 16, 16, 16, float> acc[8];
    #pragma unroll
    for (int n = 0; n < 8; n++) wmma::fill_fragment(acc[n], 0.f);

    for (int k = 0; k < K; k += 16) {
        wmma::fragment<wmma::matrix_a, 16, 16, 16, __nv_bfloat16, wmma::row_major> fa;
        wmma::load_matrix_sync(fa, &sA[(w * 16) * pitch + k], pitch);
        #pragma unroll
        for (int n = 0; n < 8; n++) {
            wmma::fragment<wmma::matrix_b, 16, 16, 16, __nv_bfloat16, wmma::col_major> fb;
            wmma::load_matrix_sync(fb, &sB[(n * 16) * pitch + k], pitch);
            wmma::mma_sync(acc[n], fa, fb, acc[n]);
        }
    }

    // ---- epilogue: stage to smem, fused stats, fp16 store ----
    __syncthreads();
    float* Hs = (float*)smb;                       // [128][128] = 64 KB
    #pragma unroll
    for (int n = 0; n < 8; n++)
        wmma::store_matrix_sync(&Hs[(w * 16) * HID + n * 16], acc[n], HID,
                                wmma::mem_row_major);
    __syncthreads();

    __half* H  = (layer == 1) ? g_h1pre : g_h2pre;
    float*  st = (layer == 1) ? g_stats1 : g_stats2;

    int col = tid & 127, half = tid >> 7;
    float s = 0.f, ss = 0.f;
    #pragma unroll 8
    for (int r = 0; r < 64; r++) {
        float vv = Hs[(half * 64 + r) * HID + col];
        s += vv;
        ss += vv * vv;
    }
    atomicAdd(&st[col], s);
    atomicAdd(&st[HID + col], ss);

    for (int i = tid; i < 128 * 32; i += 256) {
        int r = i >> 5, c = i & 31;
        float4 f = ((const float4*)&Hs[r * HID])[c];
        __half2 h0 = __floats2half2_rn(f.x, f.y);
        __half2 h1 = __floats2half2_rn(f.z, f.w);
        uint2 o;
        o.x = *(uint32_t*)&h0;
        o.y = *(uint32_t*)&h1;
        ((uint2*)&H[(m0 + r) * HID])[c] = o;
    }
}

// ---------------- norm / readout ---------------------------------------------
// 2048 blocks x 64 rows; fp16 input; rsqrt(deg_src) inline.
__global__ void k_norm(int layer,
                       const float* __restrict__ gamma, const float* __restrict__ beta,
                       const float* __restrict__ alpha) {
    __shared__ float sRs[64];
    int j = threadIdx.x;
    int b = blockIdx.x;
    const float* stats = (layer == 1) ? g_stats1 : g_stats2;
    const __half* hpre = (layer == 1) ? g_h1pre : g_h2pre;
    int rcol   = (layer == 1) ? 0 : HID;
    int writeH = (layer == 1) ? 1 : 0;

    if (writeH && j < 64) sRs[j] = rsqrtf((float)max(g_deg_src[b * 64 + j], 1));
    __syncthreads();

    const float invN = 1.0f / (float)N_NODES;
    float mu  = stats[j] * invN;
    float ex2 = stats[HID + j] * invN;
    float al  = alpha[j];
    float var = ex2 + mu * mu * (al * al - 2.f * al);
    float istd = rsqrtf(var + EPSV);
    float ga = gamma[j] * istd;
    float be = beta[j];
    float amu = al * mu;

    int g = (b * 64) / P_NODES;
    const __half* in = &hpre[(size_t)b * 64 * HID];
    __half* out = &g_h1h[(size_t)b * 64 * HID];
    float rsum = 0.f;
    #pragma unroll 4
    for (int r = 0; r < 64; r++) {
        float v = __half2float(in[r * HID + j]);
        float c = (v - amu) * ga + be;
        float y = c > 0.f ? c : SLOPE * c;
        if (writeH) out[r * HID + j] = __float2half(y * sRs[r]);
        rsum += y;
    }
    atomicAdd(&g_r[g * (2 * HID) + rcol + j], rsum);
}

__global__ void k_final(const float* __restrict__ Wc, float* __restrict__ out) {
    int t = threadIdx.x;
    int b = t >> 4, o = t & 15;
    const float* rb = &g_r[b * 2 * HID];
    const float* wr = &Wc[o * 2 * HID];
    float s = 0.f;
    #pragma unroll 8
    for (int k = 0; k < 2 * HID; k++) s += rb[k] * wr[k];
    out[b * OUT_DIM + o] = s * (1.0f / (float)P_NODES);
}

// ---------------- launch -----------------------------------------------------

extern "C" void kernel_launch(void* const* d_in, const int* in_sizes, int n_in,
                              void* d_out, int out_size) {
    const float* features = (const float*)d_in[0];
    const float* ew       = (const float*)d_in[1];
    const int*   src      = (const int*)d_in[2];
    const int*   dst      = (const int*)d_in[3];
    const float* W1       = (const float*)d_in[4];
    const float* W2       = (const float*)d_in[5];
    const float* Wc       = (const float*)d_in[6];
    const float* gamma1   = (const float*)d_in[7];
    const float* beta1    = (const float*)d_in[8];
    const float* alpha1   = (const float*)d_in[9];
    const float* gamma2   = (const float*)d_in[10];
    const float* beta2    = (const float*)d_in[11];
    const float* alpha2   = (const float*)d_in[12];
    float* out = (float*)d_out;

    const int smem1 = 128 * 128 * 4;               // 65536 (>= tiles for K=64)
    const int smem2 = 2 * 128 * (HID + 8) * 2;     // 69632
    cudaFuncSetAttribute(k_gemm, cudaFuncAttributeMaxDynamicSharedMemorySize, smem2);

    k_zero<<<N_NODES / 256, 256>>>();
    k_build<<<E_EDGES / 1024, 256>>>(src, dst, ew);
    k_prep<<<4097, 256>>>(features, W1, W2);

    k_gemm<<<N_NODES / 128, 256, smem1>>>(1);
    k_norm<<<2048, 128>>>(1, gamma1, beta1, alpha1);

    k_gemm<<<N_NODES / 128, 256, smem2>>>(2);
    k_norm<<<2048, 128>>>(2, gamma2, beta2, alpha2);

    k_final<<<1, 512>>>(Wc, out);
}

// round 14
// speedup vs baseline: 1.2632x; 1.2632x over previous
#include <cuda_runtime.h>
#include <cuda_fp16.h>
#include <cuda_bf16.h>
#include <mma.h>
#include <cstdint>

using namespace nvcuda;

#define N_NODES 131072
#define P_NODES 4096
#define B_GR    32
#define E_EDGES 2097152
#define IN_DIM  64
#define HID     128
#define OUT_DIM 16
#define CAP     64
#define EPSV    1e-5f
#define SLOPE   0.01f

// ---------------- scratch (device globals; no allocations allowed) ----------
__device__ int    g_deg_src[N_NODES];
__device__ int    g_cursor[N_NODES];                 // dst degree after build
__device__ int2   g_csre[(size_t)N_NODES * CAP];     // packed {src, raw ew}
__device__ __nv_bfloat16 g_x16[(size_t)N_NODES * IN_DIM];   // bf16 features * rs_src
__device__ __nv_bfloat16 g_agg1[(size_t)N_NODES * IN_DIM];
__device__ __nv_bfloat16 g_agg2[(size_t)N_NODES * HID];
__device__ __nv_bfloat16 g_w1t[HID * IN_DIM];        // W1^T  [n][k]
__device__ __nv_bfloat16 g_w2t[HID * HID];           // W2^T  [n][k]
__device__ __half g_h1pre[(size_t)N_NODES * HID];    // pre-norm h1 (fp16)
__device__ __half g_h1h[(size_t)N_NODES * HID];      // normalized h1 * rs_src (fp16)
__device__ __half g_h2pre[(size_t)N_NODES * HID];    // pre-norm h2 (fp16)
__device__ float  g_stats1[2 * HID];
__device__ float  g_stats2[2 * HID];
__device__ float  g_r[B_GR * 2 * HID];

// ---------------- setup -----------------------------------------------------

__global__ void k_zero() {
    int i = blockIdx.x * blockDim.x + threadIdx.x;
    if (i < N_NODES) { g_deg_src[i] = 0; g_cursor[i] = 0; }
    if (i < 2 * HID) { g_stats1[i] = 0.f; g_stats2[i] = 0.f; }
    if (i < B_GR * 2 * HID) { g_r[i] = 0.f; }
}

// 4 edges/thread: vector loads + independent atomic chains; writes packed CSR.
__global__ __launch_bounds__(256) void k_build(const int* __restrict__ src,
                                               const int* __restrict__ dst,
                                               const float* __restrict__ ew) {
    int e4 = (blockIdx.x * 256 + threadIdx.x) * 4;
    int4   s4 = *(const int4*)&src[e4];
    int4   d4 = *(const int4*)&dst[e4];
    float4 w4 = *(const float4*)&ew[e4];
    int p0 = atomicAdd(&g_cursor[d4.x], 1);
    int p1 = atomicAdd(&g_cursor[d4.y], 1);
    int p2 = atomicAdd(&g_cursor[d4.z], 1);
    int p3 = atomicAdd(&g_cursor[d4.w], 1);
    atomicAdd(&g_deg_src[s4.x], 1);
    atomicAdd(&g_deg_src[s4.y], 1);
    atomicAdd(&g_deg_src[s4.z], 1);
    atomicAdd(&g_deg_src[s4.w], 1);
    if (p0 < CAP) g_csre[(size_t)d4.x * CAP + p0] = make_int2(s4.x, __float_as_int(w4.x));
    if (p1 < CAP) g_csre[(size_t)d4.y * CAP + p1] = make_int2(s4.y, __float_as_int(w4.y));
    if (p2 < CAP) g_csre[(size_t)d4.z * CAP + p2] = make_int2(s4.z, __float_as_int(w4.z));
    if (p3 < CAP) g_csre[(size_t)d4.w * CAP + p3] = make_int2(s4.w, __float_as_int(w4.w));
}

// blocks [0,4096): features -> bf16 * rsqrt(deg_src); 8 floats/thread.
// block 4096: transpose W1,W2 to bf16 K-major.
__global__ __launch_bounds__(256) void k_prep(const float* __restrict__ x,
                                              const float* __restrict__ W1,
                                              const float* __restrict__ W2) {
    int b = blockIdx.x, t = threadIdx.x;
    if (b < 4096) {
        int i0 = b * 2048 + t * 8;
        int row = i0 >> 6;
        float rs = rsqrtf((float)max(g_deg_src[row], 1));
        float4 a = *(const float4*)&x[i0];
        float4 c = *(const float4*)&x[i0 + 4];
        uint4 o;
        __nv_bfloat162 b0 = __floats2bfloat162_rn(a.x * rs, a.y * rs);
        __nv_bfloat162 b1 = __floats2bfloat162_rn(a.z * rs, a.w * rs);
        __nv_bfloat162 b2 = __floats2bfloat162_rn(c.x * rs, c.y * rs);
        __nv_bfloat162 b3 = __floats2bfloat162_rn(c.z * rs, c.w * rs);
        o.x = *(uint32_t*)&b0; o.y = *(uint32_t*)&b1;
        o.z = *(uint32_t*)&b2; o.w = *(uint32_t*)&b3;
        *(uint4*)&g_x16[i0] = o;
    } else {
        for (int i = t; i < HID * IN_DIM; i += 256) {
            int n = i / IN_DIM, k = i % IN_DIM;
            g_w1t[i] = __float2bfloat16(W1[k * HID + n]);
        }
        for (int i = t; i < HID * HID; i += 256) {
            int n = i / HID, k = i % HID;
            g_w2t[i] = __float2bfloat16(W2[k * HID + n]);
        }
    }
}

// ---------------- aggregation: wide-load gather ------------------------------
// agg1: row = 128B = 8 lanes x uint4. Quarter-warp per edge row; 4 edges per
// LDG.128; batch of 8 LDGs covers 32 edge slots. Reduce via shfl_xor(8,16).
__global__ __launch_bounds__(256) void k_agg1() {
    int tid = threadIdx.x, w = tid >> 5, lane = tid & 31;
    int qw = lane >> 3, fl = lane & 7;             // quarter-warp id, feature lane
    int vb = blockIdx.x * 32 + w * 4;
    #pragma unroll
    for (int nn = 0; nn < 4; nn++) {
        int v = vb + nn;
        int degf = g_cursor[v];
        int deg  = min(degf, CAP);
        const int2* ce = &g_csre[(size_t)v * CAP];
        float acc[8];
        #pragma unroll
        for (int f = 0; f < 8; f++) acc[f] = 0.f;
        for (int i = 0; i < deg; i += 32) {
            uint4 uu[8];
            float wt[8];
            #pragma unroll
            for (int u = 0; u < 8; u++) {
                int ei = i + 4 * u + qw;
                int j  = min(ei, deg - 1);
                int2 e = __ldg(&ce[j]);
                wt[u]  = (ei < deg) ? __int_as_float(e.y) : 0.f;
                uu[u]  = *(const uint4*)(g_x16 + (size_t)e.x * IN_DIM + fl * 8);
            }
            #pragma unroll
            for (int u = 0; u < 8; u++) {
                float2 p0 = __bfloat1622float2(*(const __nv_bfloat162*)&uu[u].x);
                float2 p1 = __bfloat1622float2(*(const __nv_bfloat162*)&uu[u].y);
                float2 p2 = __bfloat1622float2(*(const __nv_bfloat162*)&uu[u].z);
                float2 p3 = __bfloat1622float2(*(const __nv_bfloat162*)&uu[u].w);
                acc[0] += wt[u] * p0.x; acc[1] += wt[u] * p0.y;
                acc[2] += wt[u] * p1.x; acc[3] += wt[u] * p1.y;
                acc[4] += wt[u] * p2.x; acc[5] += wt[u] * p2.y;
                acc[6] += wt[u] * p3.x; acc[7] += wt[u] * p3.y;
            }
        }
        #pragma unroll
        for (int f = 0; f < 8; f++) {
            acc[f] += __shfl_xor_sync(0xffffffffu, acc[f], 8);
            acc[f] += __shfl_xor_sync(0xffffffffu, acc[f], 16);
        }
        if (qw == 0) {
            float rd = rsqrtf((float)max(degf, 1));
            uint4 o;
            __nv_bfloat162 c0 = __floats2bfloat162_rn(acc[0] * rd, acc[1] * rd);
            __nv_bfloat162 c1 = __floats2bfloat162_rn(acc[2] * rd, acc[3] * rd);
            __nv_bfloat162 c2 = __floats2bfloat162_rn(acc[4] * rd, acc[5] * rd);
            __nv_bfloat162 c3 = __floats2bfloat162_rn(acc[6] * rd, acc[7] * rd);
            o.x = *(uint32_t*)&c0; o.y = *(uint32_t*)&c1;
            o.z = *(uint32_t*)&c2; o.w = *(uint32_t*)&c3;
            *(uint4*)&g_agg1[(size_t)v * IN_DIM + fl * 8] = o;
        }
    }
}

// agg2: row = 256B = 16 lanes x uint4. Half-warp per edge row; 2 edges per
// LDG.128; batch of 8 LDGs covers 16 edge slots. Reduce via shfl_xor(16).
__global__ __launch_bounds__(256) void k_agg2() {
    int tid = threadIdx.x, w = tid >> 5, lane = tid & 31;
    int hw = lane >> 4, fl = lane & 15;
    int vb = blockIdx.x * 32 + w * 4;
    #pragma unroll
    for (int nn = 0; nn < 4; nn++) {
        int v = vb + nn;
        int degf = g_cursor[v];
        int deg  = min(degf, CAP);
        const int2* ce = &g_csre[(size_t)v * CAP];
        float acc[8];
        #pragma unroll
        for (int f = 0; f < 8; f++) acc[f] = 0.f;
        for (int i = 0; i < deg; i += 16) {
            uint4 uu[8];
            float wt[8];
            #pragma unroll
            for (int u = 0; u < 8; u++) {
                int ei = i + 2 * u + hw;
                int j  = min(ei, deg - 1);
                int2 e = __ldg(&ce[j]);
                wt[u]  = (ei < deg) ? __int_as_float(e.y) : 0.f;
                uu[u]  = *(const uint4*)(g_h1h + (size_t)e.x * HID + fl * 8);
            }
            #pragma unroll
            for (int u = 0; u < 8; u++) {
                float2 p0 = __half22float2(*(const __half2*)&uu[u].x);
                float2 p1 = __half22float2(*(const __half2*)&uu[u].y);
                float2 p2 = __half22float2(*(const __half2*)&uu[u].z);
                float2 p3 = __half22float2(*(const __half2*)&uu[u].w);
                acc[0] += wt[u] * p0.x; acc[1] += wt[u] * p0.y;
                acc[2] += wt[u] * p1.x; acc[3] += wt[u] * p1.y;
                acc[4] += wt[u] * p2.x; acc[5] += wt[u] * p2.y;
                acc[6] += wt[u] * p3.x; acc[7] += wt[u] * p3.y;
            }
        }
        #pragma unroll
        for (int f = 0; f < 8; f++)
            acc[f] += __shfl_xor_sync(0xffffffffu, acc[f], 16);
        if (hw == 0) {
            float rd = rsqrtf((float)max(degf, 1));
            uint4 o;
            __nv_bfloat162 c0 = __floats2bfloat162_rn(acc[0] * rd, acc[1] * rd);
            __nv_bfloat162 c1 = __floats2bfloat162_rn(acc[2] * rd, acc[3] * rd);
            __nv_bfloat162 c2 = __floats2bfloat162_rn(acc[4] * rd, acc[5] * rd);
            __nv_bfloat162 c3 = __floats2bfloat162_rn(acc[6] * rd, acc[7] * rd);
            o.x = *(uint32_t*)&c0; o.y = *(uint32_t*)&c1;
            o.z = *(uint32_t*)&c2; o.w = *(uint32_t*)&c3;
            *(uint4*)&g_agg2[(size_t)v * HID + fl * 8] = o;
        }
    }
}

// ---------------- WMMA GEMM + fused GraphNorm stats --------------------------
__global__ __launch_bounds__(256) void k_gemm(int layer) {
    extern __shared__ __nv_bfloat16 smb[];
    const int K   = (layer == 1) ? IN_DIM : HID;
    const int pitch = K + 8;
    __nv_bfloat16* sA = smb;                       // [128][pitch]
    __nv_bfloat16* sB = smb + 128 * pitch;         // [128][pitch]
    const __nv_bfloat16* Ag = (layer == 1) ? g_agg1 : g_agg2;
    const __nv_bfloat16* Bg = (layer == 1) ? g_w1t  : g_w2t;
    int tid = threadIdx.x;
    size_t m0 = (size_t)blockIdx.x * 128;

    int vecs = K / 8;                              // uint4 = 8 bf16
    for (int i = tid; i < 128 * vecs; i += 256) {
        int r = i / vecs, c = i % vecs;
        *(uint4*)&sA[r * pitch + c * 8] = *(const uint4*)&Ag[(m0 + r) * K + c * 8];
        *(uint4*)&sB[r * pitch + c * 8] = *(const uint4*)&Bg[(size_t)r * K + c * 8];
    }
    __syncthreads();

    int w = tid >> 5;
    wmma::fragment<wmma::accumulator, 16, 16, 16, float> acc[8];
    #pragma unroll
    for (int n = 0; n < 8; n++) wmma::fill_fragment(acc[n], 0.f);

    for (int k = 0; k < K; k += 16) {
        wmma::fragment<wmma::matrix_a, 16, 16, 16, __nv_bfloat16, wmma::row_major> fa;
        wmma::load_matrix_sync(fa, &sA[(w * 16) * pitch + k], pitch);
        #pragma unroll
        for (int n = 0; n < 8; n++) {
            wmma::fragment<wmma::matrix_b, 16, 16, 16, __nv_bfloat16, wmma::col_major> fb;
            wmma::load_matrix_sync(fb, &sB[(n * 16) * pitch + k], pitch);
            wmma::mma_sync(acc[n], fa, fb, acc[n]);
        }
    }

    // ---- epilogue: stage to smem, fused stats, fp16 store ----
    __syncthreads();
    float* Hs = (float*)smb;                       // [128][128] = 64 KB
    #pragma unroll
    for (int n = 0; n < 8; n++)
        wmma::store_matrix_sync(&Hs[(w * 16) * HID + n * 16], acc[n], HID,
                                wmma::mem_row_major);
    __syncthreads();

    __half* H  = (layer == 1) ? g_h1pre : g_h2pre;
    float*  st = (layer == 1) ? g_stats1 : g_stats2;

    int col = tid & 127, half = tid >> 7;
    float s = 0.f, ss = 0.f;
    #pragma unroll 8
    for (int r = 0; r < 64; r++) {
        float vv = Hs[(half * 64 + r) * HID + col];
        s += vv;
        ss += vv * vv;
    }
    atomicAdd(&st[col], s);
    atomicAdd(&st[HID + col], ss);

    for (int i = tid; i < 128 * 32; i += 256) {
        int r = i >> 5, c = i & 31;
        float4 f = ((const float4*)&Hs[r * HID])[c];
        __half2 h0 = __floats2half2_rn(f.x, f.y);
        __half2 h1 = __floats2half2_rn(f.z, f.w);
        uint2 o;
        o.x = *(uint32_t*)&h0;
        o.y = *(uint32_t*)&h1;
        ((uint2*)&H[(m0 + r) * HID])[c] = o;
    }
}

// ---------------- norm / readout ---------------------------------------------
// 2048 blocks x 64 rows; fp16 input; rsqrt(deg_src) inline.
__global__ void k_norm(int layer,
                       const float* __restrict__ gamma, const float* __restrict__ beta,
                       const float* __restrict__ alpha) {
    __shared__ float sRs[64];
    int j = threadIdx.x;
    int b = blockIdx.x;
    const float* stats = (layer == 1) ? g_stats1 : g_stats2;
    const __half* hpre = (layer == 1) ? g_h1pre : g_h2pre;
    int rcol   = (layer == 1) ? 0 : HID;
    int writeH = (layer == 1) ? 1 : 0;

    if (writeH && j < 64) sRs[j] = rsqrtf((float)max(g_deg_src[b * 64 + j], 1));
    __syncthreads();

    const float invN = 1.0f / (float)N_NODES;
    float mu  = stats[j] * invN;
    float ex2 = stats[HID + j] * invN;
    float al  = alpha[j];
    float var = ex2 + mu * mu * (al * al - 2.f * al);
    float istd = rsqrtf(var + EPSV);
    float ga = gamma[j] * istd;
    float be = beta[j];
    float amu = al * mu;

    int g = (b * 64) / P_NODES;
    const __half* in = &hpre[(size_t)b * 64 * HID];
    __half* out = &g_h1h[(size_t)b * 64 * HID];
    float rsum = 0.f;
    #pragma unroll 4
    for (int r = 0; r < 64; r++) {
        float v = __half2float(in[r * HID + j]);
        float c = (v - amu) * ga + be;
        float y = c > 0.f ? c : SLOPE * c;
        if (writeH) out[r * HID + j] = __float2half(y * sRs[r]);
        rsum += y;
    }
    atomicAdd(&g_r[g * (2 * HID) + rcol + j], rsum);
}

__global__ void k_final(const float* __restrict__ Wc, float* __restrict__ out) {
    int t = threadIdx.x;
    int b = t >> 4, o = t & 15;
    const float* rb = &g_r[b * 2 * HID];
    const float* wr = &Wc[o * 2 * HID];
    float s = 0.f;
    #pragma unroll 8
    for (int k = 0; k < 2 * HID; k++) s += rb[k] * wr[k];
    out[b * OUT_DIM + o] = s * (1.0f / (float)P_NODES);
}

// ---------------- launch -----------------------------------------------------

extern "C" void kernel_launch(void* const* d_in, const int* in_sizes, int n_in,
                              void* d_out, int out_size) {
    const float* features = (const float*)d_in[0];
    const float* ew       = (const float*)d_in[1];
    const int*   src      = (const int*)d_in[2];
    const int*   dst      = (const int*)d_in[3];
    const float* W1       = (const float*)d_in[4];
    const float* W2       = (const float*)d_in[5];
    const float* Wc       = (const float*)d_in[6];
    const float* gamma1   = (const float*)d_in[7];
    const float* beta1    = (const float*)d_in[8];
    const float* alpha1   = (const float*)d_in[9];
    const float* gamma2   = (const float*)d_in[10];
    const float* beta2    = (const float*)d_in[11];
    const float* alpha2   = (const float*)d_in[12];
    float* out = (float*)d_out;

    const int smem1 = 128 * 128 * 4;               // 65536
    const int smem2 = 2 * 128 * (HID + 8) * 2;     // 69632
    cudaFuncSetAttribute(k_gemm, cudaFuncAttributeMaxDynamicSharedMemorySize, smem2);

    k_zero<<<N_NODES / 256, 256>>>();
    k_build<<<E_EDGES / 1024, 256>>>(src, dst, ew);
    k_prep<<<4097, 256>>>(features, W1, W2);

    k_agg1<<<N_NODES / 32, 256>>>();
    k_gemm<<<N_NODES / 128, 256, smem1>>>(1);
    k_norm<<<2048, 128>>>(1, gamma1, beta1, alpha1);

    k_agg2<<<N_NODES / 32, 256>>>();
    k_gemm<<<N_NODES / 128, 256, smem2>>>(2);
    k_norm<<<2048, 128>>>(2, gamma2, beta2, alpha2);

    k_final<<<1, 512>>>(Wc, out);
}

// round 15
// speedup vs baseline: 1.4273x; 1.1299x over previous
#include <cuda_runtime.h>
#include <cuda_fp16.h>
#include <mma.h>
#include <cstdint>

using namespace nvcuda;

#define N_NODES 131072
#define P_NODES 4096
#define B_GR    32
#define E_EDGES 2097152
#define IN_DIM  64
#define HID     128
#define OUT_DIM 16
#define CAP     64
#define EPSV    1e-5f
#define SLOPE   0.01f

// ---------------- scratch (device globals; no allocations allowed) ----------
__device__ int    g_deg_src[N_NODES];
__device__ int    g_cursor[N_NODES];                 // dst degree after build
__device__ int2   g_csre[(size_t)N_NODES * CAP];     // packed {src, half2(ew,ew)}
__device__ __half g_x16[(size_t)N_NODES * IN_DIM];   // fp16 features * rs_src
__device__ __half g_agg1[(size_t)N_NODES * IN_DIM];
__device__ __half g_agg2[(size_t)N_NODES * HID];
__device__ __half g_w1t[HID * IN_DIM];               // W1^T  [n][k] fp16
__device__ __half g_w2t[HID * HID];                  // W2^T  [n][k] fp16
__device__ __half g_h1pre[(size_t)N_NODES * HID];    // pre-norm h1 (fp16)
__device__ __half g_h1h[(size_t)N_NODES * HID];      // normalized h1 * rs_src (fp16)
__device__ __half g_h2pre[(size_t)N_NODES * HID];    // pre-norm h2 (fp16)
__device__ float  g_stats1[2 * HID];
__device__ float  g_stats2[2 * HID];
__device__ float  g_r[B_GR * 2 * HID];

// ---------------- setup -----------------------------------------------------

__global__ void k_zero() {
    int i = blockIdx.x * blockDim.x + threadIdx.x;
    if (i < N_NODES) { g_deg_src[i] = 0; g_cursor[i] = 0; }
    if (i < 2 * HID) { g_stats1[i] = 0.f; g_stats2[i] = 0.f; }
    if (i < B_GR * 2 * HID) { g_r[i] = 0.f; }
}

// 4 edges/thread; weight pre-converted to duplicated half2 (kills per-edge cvt
// in both aggregation kernels).
__global__ __launch_bounds__(256) void k_build(const int* __restrict__ src,
                                               const int* __restrict__ dst,
                                               const float* __restrict__ ew) {
    int e4 = (blockIdx.x * 256 + threadIdx.x) * 4;
    int4   s4 = *(const int4*)&src[e4];
    int4   d4 = *(const int4*)&dst[e4];
    float4 w4 = *(const float4*)&ew[e4];
    int p0 = atomicAdd(&g_cursor[d4.x], 1);
    int p1 = atomicAdd(&g_cursor[d4.y], 1);
    int p2 = atomicAdd(&g_cursor[d4.z], 1);
    int p3 = atomicAdd(&g_cursor[d4.w], 1);
    atomicAdd(&g_deg_src[s4.x], 1);
    atomicAdd(&g_deg_src[s4.y], 1);
    atomicAdd(&g_deg_src[s4.z], 1);
    atomicAdd(&g_deg_src[s4.w], 1);
    uint32_t h0 = (uint32_t)__half_as_ushort(__float2half(w4.x)) * 0x00010001u;
    uint32_t h1 = (uint32_t)__half_as_ushort(__float2half(w4.y)) * 0x00010001u;
    uint32_t h2 = (uint32_t)__half_as_ushort(__float2half(w4.z)) * 0x00010001u;
    uint32_t h3 = (uint32_t)__half_as_ushort(__float2half(w4.w)) * 0x00010001u;
    if (p0 < CAP) g_csre[(size_t)d4.x * CAP + p0] = make_int2(s4.x, (int)h0);
    if (p1 < CAP) g_csre[(size_t)d4.y * CAP + p1] = make_int2(s4.y, (int)h1);
    if (p2 < CAP) g_csre[(size_t)d4.z * CAP + p2] = make_int2(s4.z, (int)h2);
    if (p3 < CAP) g_csre[(size_t)d4.w * CAP + p3] = make_int2(s4.w, (int)h3);
}

// blocks [0,4096): features -> fp16 * rsqrt(deg_src); 8 floats/thread.
// block 4096: transpose W1,W2 to fp16 K-major.
__global__ __launch_bounds__(256) void k_prep(const float* __restrict__ x,
                                              const float* __restrict__ W1,
                                              const float* __restrict__ W2) {
    int b = blockIdx.x, t = threadIdx.x;
    if (b < 4096) {
        int i0 = b * 2048 + t * 8;
        int row = i0 >> 6;
        float rs = rsqrtf((float)max(g_deg_src[row], 1));
        float4 a = *(const float4*)&x[i0];
        float4 c = *(const float4*)&x[i0 + 4];
        uint4 o;
        __half2 b0 = __floats2half2_rn(a.x * rs, a.y * rs);
        __half2 b1 = __floats2half2_rn(a.z * rs, a.w * rs);
        __half2 b2 = __floats2half2_rn(c.x * rs, c.y * rs);
        __half2 b3 = __floats2half2_rn(c.z * rs, c.w * rs);
        o.x = *(uint32_t*)&b0; o.y = *(uint32_t*)&b1;
        o.z = *(uint32_t*)&b2; o.w = *(uint32_t*)&b3;
        *(uint4*)&g_x16[i0] = o;
    } else {
        for (int i = t; i < HID * IN_DIM; i += 256) {
            int n = i / IN_DIM, k = i % IN_DIM;
            g_w1t[i] = __float2half(W1[k * HID + n]);
        }
        for (int i = t; i < HID * HID; i += 256) {
            int n = i / HID, k = i % HID;
            g_w2t[i] = __float2half(W2[k * HID + n]);
        }
    }
}

// ---------------- aggregation: wide-load gather, HFMA2 accumulation ----------
// agg1: row = 128B = 8 lanes x uint4 (8 fp16). Quarter-warp per edge row.
__global__ __launch_bounds__(256) void k_agg1() {
    int tid = threadIdx.x, w = tid >> 5, lane = tid & 31;
    int qw = lane >> 3, fl = lane & 7;
    int vb = blockIdx.x * 32 + w * 4;
    #pragma unroll
    for (int nn = 0; nn < 4; nn++) {
        int v = vb + nn;
        int degf = g_cursor[v];
        int deg  = min(degf, CAP);
        const int2* ce = &g_csre[(size_t)v * CAP];
        __half2 ac0 = __float2half2_rn(0.f), ac1 = ac0, ac2 = ac0, ac3 = ac0;
        for (int i = 0; i < deg; i += 32) {
            uint4    uu[8];
            uint32_t wp[8];
            #pragma unroll
            for (int u = 0; u < 8; u++) {
                int ei = i + 4 * u + qw;
                int j  = min(ei, deg - 1);
                int2 e = __ldg(&ce[j]);
                wp[u]  = (ei < deg) ? (uint32_t)e.y : 0u;
                uu[u]  = *(const uint4*)(g_x16 + (size_t)e.x * IN_DIM + fl * 8);
            }
            #pragma unroll
            for (int u = 0; u < 8; u++) {
                __half2 w2 = *(__half2*)&wp[u];
                ac0 = __hfma2(w2, *(const __half2*)&uu[u].x, ac0);
                ac1 = __hfma2(w2, *(const __half2*)&uu[u].y, ac1);
                ac2 = __hfma2(w2, *(const __half2*)&uu[u].z, ac2);
                ac3 = __hfma2(w2, *(const __half2*)&uu[u].w, ac3);
            }
        }
        float acc[8];
        { float2 f;
          f = __half22float2(ac0); acc[0] = f.x; acc[1] = f.y;
          f = __half22float2(ac1); acc[2] = f.x; acc[3] = f.y;
          f = __half22float2(ac2); acc[4] = f.x; acc[5] = f.y;
          f = __half22float2(ac3); acc[6] = f.x; acc[7] = f.y; }
        #pragma unroll
        for (int f = 0; f < 8; f++) {
            acc[f] += __shfl_xor_sync(0xffffffffu, acc[f], 8);
            acc[f] += __shfl_xor_sync(0xffffffffu, acc[f], 16);
        }
        if (qw == 0) {
            float rd = rsqrtf((float)max(degf, 1));
            uint4 o;
            __half2 c0 = __floats2half2_rn(acc[0] * rd, acc[1] * rd);
            __half2 c1 = __floats2half2_rn(acc[2] * rd, acc[3] * rd);
            __half2 c2 = __floats2half2_rn(acc[4] * rd, acc[5] * rd);
            __half2 c3 = __floats2half2_rn(acc[6] * rd, acc[7] * rd);
            o.x = *(uint32_t*)&c0; o.y = *(uint32_t*)&c1;
            o.z = *(uint32_t*)&c2; o.w = *(uint32_t*)&c3;
            *(uint4*)&g_agg1[(size_t)v * IN_DIM + fl * 8] = o;
        }
    }
}

// agg2: row = 256B = 16 lanes x uint4. Half-warp per edge row.
__global__ __launch_bounds__(256) void k_agg2() {
    int tid = threadIdx.x, w = tid >> 5, lane = tid & 31;
    int hw = lane >> 4, fl = lane & 15;
    int vb = blockIdx.x * 32 + w * 4;
    #pragma unroll
    for (int nn = 0; nn < 4; nn++) {
        int v = vb + nn;
        int degf = g_cursor[v];
        int deg  = min(degf, CAP);
        const int2* ce = &g_csre[(size_t)v * CAP];
        __half2 ac0 = __float2half2_rn(0.f), ac1 = ac0, ac2 = ac0, ac3 = ac0;
        for (int i = 0; i < deg; i += 16) {
            uint4    uu[8];
            uint32_t wp[8];
            #pragma unroll
            for (int u = 0; u < 8; u++) {
                int ei = i + 2 * u + hw;
                int j  = min(ei, deg - 1);
                int2 e = __ldg(&ce[j]);
                wp[u]  = (ei < deg) ? (uint32_t)e.y : 0u;
                uu[u]  = *(const uint4*)(g_h1h + (size_t)e.x * HID + fl * 8);
            }
            #pragma unroll
            for (int u = 0; u < 8; u++) {
                __half2 w2 = *(__half2*)&wp[u];
                ac0 = __hfma2(w2, *(const __half2*)&uu[u].x, ac0);
                ac1 = __hfma2(w2, *(const __half2*)&uu[u].y, ac1);
                ac2 = __hfma2(w2, *(const __half2*)&uu[u].z, ac2);
                ac3 = __hfma2(w2, *(const __half2*)&uu[u].w, ac3);
            }
        }
        float acc[8];
        { float2 f;
          f = __half22float2(ac0); acc[0] = f.x; acc[1] = f.y;
          f = __half22float2(ac1); acc[2] = f.x; acc[3] = f.y;
          f = __half22float2(ac2); acc[4] = f.x; acc[5] = f.y;
          f = __half22float2(ac3); acc[6] = f.x; acc[7] = f.y; }
        #pragma unroll
        for (int f = 0; f < 8; f++)
            acc[f] += __shfl_xor_sync(0xffffffffu, acc[f], 16);
        if (hw == 0) {
            float rd = rsqrtf((float)max(degf, 1));
            uint4 o;
            __half2 c0 = __floats2half2_rn(acc[0] * rd, acc[1] * rd);
            __half2 c1 = __floats2half2_rn(acc[2] * rd, acc[3] * rd);
            __half2 c2 = __floats2half2_rn(acc[4] * rd, acc[5] * rd);
            __half2 c3 = __floats2half2_rn(acc[6] * rd, acc[7] * rd);
            o.x = *(uint32_t*)&c0; o.y = *(uint32_t*)&c1;
            o.z = *(uint32_t*)&c2; o.w = *(uint32_t*)&c3;
            *(uint4*)&g_agg2[(size_t)v * HID + fl * 8] = o;
        }
    }
}

// ---------------- WMMA (fp16) GEMM + fused GraphNorm stats -------------------
__global__ __launch_bounds__(256) void k_gemm(int layer) {
    extern __shared__ __half smb[];
    const int K   = (layer == 1) ? IN_DIM : HID;
    const int pitch = K + 8;
    __half* sA = smb;                              // [128][pitch]
    __half* sB = smb + 128 * pitch;                // [128][pitch]
    const __half* Ag = (layer == 1) ? g_agg1 : g_agg2;
    const __half* Bg = (layer == 1) ? g_w1t  : g_w2t;
    int tid = threadIdx.x;
    size_t m0 = (size_t)blockIdx.x * 128;

    int vecs = K / 8;                              // uint4 = 8 fp16
    for (int i = tid; i < 128 * vecs; i += 256) {
        int r = i / vecs, c = i % vecs;
        *(uint4*)&sA[r * pitch + c * 8] = *(const uint4*)&Ag[(m0 + r) * K + c * 8];
        *(uint4*)&sB[r * pitch + c * 8] = *(const uint4*)&Bg[(size_t)r * K + c * 8];
    }
    __syncthreads();

    int w = tid >> 5;
    wmma::fragment<wmma::accumulator, 16, 16, 16, float> acc[8];
    #pragma unroll
    for (int n = 0; n < 8; n++) wmma::fill_fragment(acc[n], 0.f);

    for (int k = 0; k < K; k += 16) {
        wmma::fragment<wmma::matrix_a, 16, 16, 16, __half, wmma::row_major> fa;
        wmma::load_matrix_sync(fa, &sA[(w * 16) * pitch + k], pitch);
        #pragma unroll
        for (int n = 0; n < 8; n++) {
            wmma::fragment<wmma::matrix_b, 16, 16, 16, __half, wmma::col_major> fb;
            wmma::load_matrix_sync(fb, &sB[(n * 16) * pitch + k], pitch);
            wmma::mma_sync(acc[n], fa, fb, acc[n]);
        }
    }

    // ---- epilogue: stage to smem, fused stats, fp16 store ----
    __syncthreads();
    float* Hs = (float*)smb;                       // [128][128] = 64 KB
    #pragma unroll
    for (int n = 0; n < 8; n++)
        wmma::store_matrix_sync(&Hs[(w * 16) * HID + n * 16], acc[n], HID,
                                wmma::mem_row_major);
    __syncthreads();

    __half* H  = (layer == 1) ? g_h1pre : g_h2pre;
    float*  st = (layer == 1) ? g_stats1 : g_stats2;

    int col = tid & 127, half = tid >> 7;
    float s = 0.f, ss = 0.f;
    #pragma unroll 8
    for (int r = 0; r < 64; r++) {
        float vv = Hs[(half * 64 + r) * HID + col];
        s += vv;
        ss += vv * vv;
    }
    atomicAdd(&st[col], s);
    atomicAdd(&st[HID + col], ss);

    for (int i = tid; i < 128 * 32; i += 256) {
        int r = i >> 5, c = i & 31;
        float4 f = ((const float4*)&Hs[r * HID])[c];
        __half2 h0 = __floats2half2_rn(f.x, f.y);
        __half2 h1 = __floats2half2_rn(f.z, f.w);
        uint2 o;
        o.x = *(uint32_t*)&h0;
        o.y = *(uint32_t*)&h1;
        ((uint2*)&H[(m0 + r) * HID])[c] = o;
    }
}

// ---------------- norm / readout ---------------------------------------------
__global__ void k_norm(int layer,
                       const float* __restrict__ gamma, const float* __restrict__ beta,
                       const float* __restrict__ alpha) {
    __shared__ float sRs[64];
    int j = threadIdx.x;
    int b = blockIdx.x;
    const float* stats = (layer == 1) ? g_stats1 : g_stats2;
    const __half* hpre = (layer == 1) ? g_h1pre : g_h2pre;
    int rcol   = (layer == 1) ? 0 : HID;
    int writeH = (layer == 1) ? 1 : 0;

    if (writeH && j < 64) sRs[j] = rsqrtf((float)max(g_deg_src[b * 64 + j], 1));
    __syncthreads();

    const float invN = 1.0f / (float)N_NODES;
    float mu  = stats[j] * invN;
    float ex2 = stats[HID + j] * invN;
    float al  = alpha[j];
    float var = ex2 + mu * mu * (al * al - 2.f * al);
    float istd = rsqrtf(var + EPSV);
    float ga = gamma[j] * istd;
    float be = beta[j];
    float amu = al * mu;

    int g = (b * 64) / P_NODES;
    const __half* in = &hpre[(size_t)b * 64 * HID];
    __half* out = &g_h1h[(size_t)b * 64 * HID];
    float rsum = 0.f;
    #pragma unroll 4
    for (int r = 0; r < 64; r++) {
        float v = __half2float(in[r * HID + j]);
        float c = (v - amu) * ga + be;
        float y = c > 0.f ? c : SLOPE * c;
        if (writeH) out[r * HID + j] = __float2half(y * sRs[r]);
        rsum += y;
    }
    atomicAdd(&g_r[g * (2 * HID) + rcol + j], rsum);
}

__global__ void k_final(const float* __restrict__ Wc, float* __restrict__ out) {
    int t = threadIdx.x;
    int b = t >> 4, o = t & 15;
    const float* rb = &g_r[b * 2 * HID];
    const float* wr = &Wc[o * 2 * HID];
    float s = 0.f;
    #pragma unroll 8
    for (int k = 0; k < 2 * HID; k++) s += rb[k] * wr[k];
    out[b * OUT_DIM + o] = s * (1.0f / (float)P_NODES);
}

// ---------------- launch -----------------------------------------------------

extern "C" void kernel_launch(void* const* d_in, const int* in_sizes, int n_in,
                              void* d_out, int out_size) {
    const float* features = (const float*)d_in[0];
    const float* ew       = (const float*)d_in[1];
    const int*   src      = (const int*)d_in[2];
    const int*   dst      = (const int*)d_in[3];
    const float* W1       = (const float*)d_in[4];
    const float* W2       = (const float*)d_in[5];
    const float* Wc       = (const float*)d_in[6];
    const float* gamma1   = (const float*)d_in[7];
    const float* beta1    = (const float*)d_in[8];
    const float* alpha1   = (const float*)d_in[9];
    const float* gamma2   = (const float*)d_in[10];
    const float* beta2    = (const float*)d_in[11];
    const float* alpha2   = (const float*)d_in[12];
    float* out = (float*)d_out;

    const int smem1 = 128 * 128 * 4;               // 65536
    const int smem2 = 2 * 128 * (HID + 8) * 2;     // 69632 > 65536
    cudaFuncSetAttribute(k_gemm, cudaFuncAttributeMaxDynamicSharedMemorySize, smem2);

    k_zero<<<N_NODES / 256, 256>>>();
    k_build<<<E_EDGES / 1024, 256>>>(src, dst, ew);
    k_prep<<<4097, 256>>>(features, W1, W2);

    k_agg1<<<N_NODES / 32, 256>>>();
    k_gemm<<<N_NODES / 128, 256, smem1>>>(1);
    k_norm<<<2048, 128>>>(1, gamma1, beta1, alpha1);

    k_agg2<<<N_NODES / 32, 256>>>();
    k_gemm<<<N_NODES / 128, 256, smem2>>>(2);
    k_norm<<<2048, 128>>>(2, gamma2, beta2, alpha2);

    k_final<<<1, 512>>>(Wc, out);
}

// round 16
// speedup vs baseline: 1.4397x; 1.0087x over previous
#include <cuda_runtime.h>
#include <cuda_fp16.h>
#include <mma.h>
#include <cstdint>

using namespace nvcuda;

#define N_NODES 131072
#define P_NODES 4096
#define B_GR    32
#define E_EDGES 2097152
#define IN_DIM  64
#define HID     128
#define OUT_DIM 16
#define CAP     64
#define EPSV    1e-5f
#define SLOPE   0.01f

// ---------------- scratch (device globals; no allocations allowed) ----------
__device__ int    g_deg_src[N_NODES];
__device__ int    g_cursor[N_NODES];                 // dst degree after build
__device__ int2   g_csre[(size_t)N_NODES * CAP];     // packed {src, half2(ew,ew)}
__device__ __half g_x16[(size_t)N_NODES * IN_DIM];   // fp16 features * rs_src
__device__ __half g_agg1[(size_t)N_NODES * IN_DIM];
__device__ __half g_agg2[(size_t)N_NODES * HID];
__device__ __half g_w1t[HID * IN_DIM];               // W1^T  [n][k] fp16
__device__ __half g_w2t[HID * HID];                  // W2^T  [n][k] fp16
__device__ __half g_h1pre[(size_t)N_NODES * HID];    // pre-norm h1 (fp16)
__device__ __half g_h1h[(size_t)N_NODES * HID];      // normalized h1 * rs_src (fp16)
__device__ __half g_h2pre[(size_t)N_NODES * HID];    // pre-norm h2 (fp16)
__device__ float  g_stats1[2 * HID];
__device__ float  g_stats2[2 * HID];
__device__ float  g_r[B_GR * 2 * HID];

__device__ __forceinline__ __half2 h2red(__half2 a, int m) {
    uint32_t u = *(uint32_t*)&a;
    uint32_t o = __shfl_xor_sync(0xffffffffu, u, m);
    return __hadd2(a, *(__half2*)&o);
}

// ---------------- setup -----------------------------------------------------

__global__ void k_zero() {
    int i = blockIdx.x * blockDim.x + threadIdx.x;
    if (i < N_NODES) { g_deg_src[i] = 0; g_cursor[i] = 0; }
    if (i < 2 * HID) { g_stats1[i] = 0.f; g_stats2[i] = 0.f; }
    if (i < B_GR * 2 * HID) { g_r[i] = 0.f; }
}

// 8 edges/thread; weight pre-converted to duplicated half2.
__global__ __launch_bounds__(256) void k_build(const int* __restrict__ src,
                                               const int* __restrict__ dst,
                                               const float* __restrict__ ew) {
    int e8 = (blockIdx.x * 256 + threadIdx.x) * 8;
    int4   sa = *(const int4*)&src[e8],   sb = *(const int4*)&src[e8 + 4];
    int4   da = *(const int4*)&dst[e8],   db = *(const int4*)&dst[e8 + 4];
    float4 wa = *(const float4*)&ew[e8],  wb = *(const float4*)&ew[e8 + 4];

    int s[8] = {sa.x, sa.y, sa.z, sa.w, sb.x, sb.y, sb.z, sb.w};
    int d[8] = {da.x, da.y, da.z, da.w, db.x, db.y, db.z, db.w};
    float wv[8] = {wa.x, wa.y, wa.z, wa.w, wb.x, wb.y, wb.z, wb.w};

    int p[8];
    #pragma unroll
    for (int u = 0; u < 8; u++) p[u] = atomicAdd(&g_cursor[d[u]], 1);
    #pragma unroll
    for (int u = 0; u < 8; u++) atomicAdd(&g_deg_src[s[u]], 1);
    #pragma unroll
    for (int u = 0; u < 8; u++) {
        uint32_t h = (uint32_t)__half_as_ushort(__float2half(wv[u])) * 0x00010001u;
        if (p[u] < CAP) g_csre[(size_t)d[u] * CAP + p[u]] = make_int2(s[u], (int)h);
    }
}

// blocks [0,4096): features -> fp16 * rsqrt(deg_src); 8 floats/thread.
// block 4096: transpose W1,W2 to fp16 K-major.
__global__ __launch_bounds__(256) void k_prep(const float* __restrict__ x,
                                              const float* __restrict__ W1,
                                              const float* __restrict__ W2) {
    int b = blockIdx.x, t = threadIdx.x;
    if (b < 4096) {
        int i0 = b * 2048 + t * 8;
        int row = i0 >> 6;
        float rs = rsqrtf((float)max(g_deg_src[row], 1));
        float4 a = *(const float4*)&x[i0];
        float4 c = *(const float4*)&x[i0 + 4];
        uint4 o;
        __half2 b0 = __floats2half2_rn(a.x * rs, a.y * rs);
        __half2 b1 = __floats2half2_rn(a.z * rs, a.w * rs);
        __half2 b2 = __floats2half2_rn(c.x * rs, c.y * rs);
        __half2 b3 = __floats2half2_rn(c.z * rs, c.w * rs);
        o.x = *(uint32_t*)&b0; o.y = *(uint32_t*)&b1;
        o.z = *(uint32_t*)&b2; o.w = *(uint32_t*)&b3;
        *(uint4*)&g_x16[i0] = o;
    } else {
        for (int i = t; i < HID * IN_DIM; i += 256) {
            int n = i / IN_DIM, k = i % IN_DIM;
            g_w1t[i] = __float2half(W1[k * HID + n]);
        }
        for (int i = t; i < HID * HID; i += 256) {
            int n = i / HID, k = i % HID;
            g_w2t[i] = __float2half(W2[k * HID + n]);
        }
    }
}

// ---------------- aggregation: wide-load gather, HFMA2 + half2 reduction -----
// agg1: row = 128B = 8 lanes x uint4 (8 fp16). Quarter-warp per edge row.
__global__ __launch_bounds__(256) void k_agg1() {
    int tid = threadIdx.x, w = tid >> 5, lane = tid & 31;
    int qw = lane >> 3, fl = lane & 7;
    int vb = blockIdx.x * 32 + w * 4;
    #pragma unroll
    for (int nn = 0; nn < 4; nn++) {
        int v = vb + nn;
        int degf = g_cursor[v];
        int deg  = min(degf, CAP);
        const int2* ce = &g_csre[(size_t)v * CAP];
        __half2 ac0 = __float2half2_rn(0.f), ac1 = ac0, ac2 = ac0, ac3 = ac0;
        for (int i = 0; i < deg; i += 32) {
            uint4    uu[8];
            uint32_t wp[8];
            #pragma unroll
            for (int u = 0; u < 8; u++) {
                int ei = i + 4 * u + qw;
                int j  = min(ei, deg - 1);
                int2 e = __ldg(&ce[j]);
                wp[u]  = (ei < deg) ? (uint32_t)e.y : 0u;
                uu[u]  = *(const uint4*)(g_x16 + (size_t)e.x * IN_DIM + fl * 8);
            }
            #pragma unroll
            for (int u = 0; u < 8; u++) {
                __half2 w2 = *(__half2*)&wp[u];
                ac0 = __hfma2(w2, *(const __half2*)&uu[u].x, ac0);
                ac1 = __hfma2(w2, *(const __half2*)&uu[u].y, ac1);
                ac2 = __hfma2(w2, *(const __half2*)&uu[u].z, ac2);
                ac3 = __hfma2(w2, *(const __half2*)&uu[u].w, ac3);
            }
        }
        // half2-domain cross-quarter-warp reduction
        ac0 = h2red(h2red(ac0, 8), 16);
        ac1 = h2red(h2red(ac1, 8), 16);
        ac2 = h2red(h2red(ac2, 8), 16);
        ac3 = h2red(h2red(ac3, 8), 16);
        if (qw == 0) {
            __half2 rdh = __float2half2_rn(rsqrtf((float)max(degf, 1)));
            ac0 = __hmul2(ac0, rdh);
            ac1 = __hmul2(ac1, rdh);
            ac2 = __hmul2(ac2, rdh);
            ac3 = __hmul2(ac3, rdh);
            uint4 o;
            o.x = *(uint32_t*)&ac0; o.y = *(uint32_t*)&ac1;
            o.z = *(uint32_t*)&ac2; o.w = *(uint32_t*)&ac3;
            *(uint4*)&g_agg1[(size_t)v * IN_DIM + fl * 8] = o;
        }
    }
}

// agg2: row = 256B = 16 lanes x uint4. Half-warp per edge row.
__global__ __launch_bounds__(256) void k_agg2() {
    int tid = threadIdx.x, w = tid >> 5, lane = tid & 31;
    int hw = lane >> 4, fl = lane & 15;
    int vb = blockIdx.x * 32 + w * 4;
    #pragma unroll
    for (int nn = 0; nn < 4; nn++) {
        int v = vb + nn;
        int degf = g_cursor[v];
        int deg  = min(degf, CAP);
        const int2* ce = &g_csre[(size_t)v * CAP];
        __half2 ac0 = __float2half2_rn(0.f), ac1 = ac0, ac2 = ac0, ac3 = ac0;
        for (int i = 0; i < deg; i += 16) {
            uint4    uu[8];
            uint32_t wp[8];
            #pragma unroll
            for (int u = 0; u < 8; u++) {
                int ei = i + 2 * u + hw;
                int j  = min(ei, deg - 1);
                int2 e = __ldg(&ce[j]);
                wp[u]  = (ei < deg) ? (uint32_t)e.y : 0u;
                uu[u]  = *(const uint4*)(g_h1h + (size_t)e.x * HID + fl * 8);
            }
            #pragma unroll
            for (int u = 0; u < 8; u++) {
                __half2 w2 = *(__half2*)&wp[u];
                ac0 = __hfma2(w2, *(const __half2*)&uu[u].x, ac0);
                ac1 = __hfma2(w2, *(const __half2*)&uu[u].y, ac1);
                ac2 = __hfma2(w2, *(const __half2*)&uu[u].z, ac2);
                ac3 = __hfma2(w2, *(const __half2*)&uu[u].w, ac3);
            }
        }
        ac0 = h2red(ac0, 16);
        ac1 = h2red(ac1, 16);
        ac2 = h2red(ac2, 16);
        ac3 = h2red(ac3, 16);
        if (hw == 0) {
            __half2 rdh = __float2half2_rn(rsqrtf((float)max(degf, 1)));
            ac0 = __hmul2(ac0, rdh);
            ac1 = __hmul2(ac1, rdh);
            ac2 = __hmul2(ac2, rdh);
            ac3 = __hmul2(ac3, rdh);
            uint4 o;
            o.x = *(uint32_t*)&ac0; o.y = *(uint32_t*)&ac1;
            o.z = *(uint32_t*)&ac2; o.w = *(uint32_t*)&ac3;
            *(uint4*)&g_agg2[(size_t)v * HID + fl * 8] = o;
        }
    }
}

// ---------------- WMMA (fp16) GEMM + fused GraphNorm stats -------------------
__global__ __launch_bounds__(256) void k_gemm(int layer) {
    extern __shared__ __half smb[];
    const int K   = (layer == 1) ? IN_DIM : HID;
    const int pitch = K + 8;
    __half* sA = smb;                              // [128][pitch]
    __half* sB = smb + 128 * pitch;                // [128][pitch]
    const __half* Ag = (layer == 1) ? g_agg1 : g_agg2;
    const __half* Bg = (layer == 1) ? g_w1t  : g_w2t;
    int tid = threadIdx.x;
    size_t m0 = (size_t)blockIdx.x * 128;

    int vecs = K / 8;                              // uint4 = 8 fp16
    for (int i = tid; i < 128 * vecs; i += 256) {
        int r = i / vecs, c = i % vecs;
        *(uint4*)&sA[r * pitch + c * 8] = *(const uint4*)&Ag[(m0 + r) * K + c * 8];
        *(uint4*)&sB[r * pitch + c * 8] = *(const uint4*)&Bg[(size_t)r * K + c * 8];
    }
    __syncthreads();

    int w = tid >> 5;
    wmma::fragment<wmma::accumulator, 16, 16, 16, float> acc[8];
    #pragma unroll
    for (int n = 0; n < 8; n++) wmma::fill_fragment(acc[n], 0.f);

    for (int k = 0; k < K; k += 16) {
        wmma::fragment<wmma::matrix_a, 16, 16, 16, __half, wmma::row_major> fa;
        wmma::load_matrix_sync(fa, &sA[(w * 16) * pitch + k], pitch);
        #pragma unroll
        for (int n = 0; n < 8; n++) {
            wmma::fragment<wmma::matrix_b, 16, 16, 16, __half, wmma::col_major> fb;
            wmma::load_matrix_sync(fb, &sB[(n * 16) * pitch + k], pitch);
            wmma::mma_sync(acc[n], fa, fb, acc[n]);
        }
    }

    // ---- epilogue: stage to smem, fused stats, fp16 store ----
    __syncthreads();
    float* Hs = (float*)smb;                       // [128][128] = 64 KB
    #pragma unroll
    for (int n = 0; n < 8; n++)
        wmma::store_matrix_sync(&Hs[(w * 16) * HID + n * 16], acc[n], HID,
                                wmma::mem_row_major);
    __syncthreads();

    __half* H  = (layer == 1) ? g_h1pre : g_h2pre;
    float*  st = (layer == 1) ? g_stats1 : g_stats2;

    int col = tid & 127, half = tid >> 7;
    float s = 0.f, ss = 0.f;
    #pragma unroll 8
    for (int r = 0; r < 64; r++) {
        float vv = Hs[(half * 64 + r) * HID + col];
        s += vv;
        ss += vv * vv;
    }
    atomicAdd(&st[col], s);
    atomicAdd(&st[HID + col], ss);

    for (int i = tid; i < 128 * 32; i += 256) {
        int r = i >> 5, c = i & 31;
        float4 f = ((const float4*)&Hs[r * HID])[c];
        __half2 h0 = __floats2half2_rn(f.x, f.y);
        __half2 h1 = __floats2half2_rn(f.z, f.w);
        uint2 o;
        o.x = *(uint32_t*)&h0;
        o.y = *(uint32_t*)&h1;
        ((uint2*)&H[(m0 + r) * HID])[c] = o;
    }
}

// ---------------- norm / readout ---------------------------------------------
__global__ void k_norm(int layer,
                       const float* __restrict__ gamma, const float* __restrict__ beta,
                       const float* __restrict__ alpha) {
    __shared__ float sRs[64];
    int j = threadIdx.x;
    int b = blockIdx.x;
    const float* stats = (layer == 1) ? g_stats1 : g_stats2;
    const __half* hpre = (layer == 1) ? g_h1pre : g_h2pre;
    int rcol   = (layer == 1) ? 0 : HID;
    int writeH = (layer == 1) ? 1 : 0;

    if (writeH && j < 64) sRs[j] = rsqrtf((float)max(g_deg_src[b * 64 + j], 1));
    __syncthreads();

    const float invN = 1.0f / (float)N_NODES;
    float mu  = stats[j] * invN;
    float ex2 = stats[HID + j] * invN;
    float al  = alpha[j];
    float var = ex2 + mu * mu * (al * al - 2.f * al);
    float istd = rsqrtf(var + EPSV);
    float ga = gamma[j] * istd;
    float be = beta[j];
    float amu = al * mu;

    int g = (b * 64) / P_NODES;
    const __half* in = &hpre[(size_t)b * 64 * HID];
    __half* out = &g_h1h[(size_t)b * 64 * HID];
    float rsum = 0.f;
    #pragma unroll 4
    for (int r = 0; r < 64; r++) {
        float v = __half2float(in[r * HID + j]);
        float c = (v - amu) * ga + be;
        float y = c > 0.f ? c : SLOPE * c;
        if (writeH) out[r * HID + j] = __float2half(y * sRs[r]);
        rsum += y;
    }
    atomicAdd(&g_r[g * (2 * HID) + rcol + j], rsum);
}

__global__ void k_final(const float* __restrict__ Wc, float* __restrict__ out) {
    int t = threadIdx.x;
    int b = t >> 4, o = t & 15;
    const float* rb = &g_r[b * 2 * HID];
    const float* wr = &Wc[o * 2 * HID];
    float s = 0.f;
    #pragma unroll 8
    for (int k = 0; k < 2 * HID; k++) s += rb[k] * wr[k];
    out[b * OUT_DIM + o] = s * (1.0f / (float)P_NODES);
}

// ---------------- launch -----------------------------------------------------

extern "C" void kernel_launch(void* const* d_in, const int* in_sizes, int n_in,
                              void* d_out, int out_size) {
    const float* features = (const float*)d_in[0];
    const float* ew       = (const float*)d_in[1];
    const int*   src      = (const int*)d_in[2];
    const int*   dst      = (const int*)d_in[3];
    const float* W1       = (const float*)d_in[4];
    const float* W2       = (const float*)d_in[5];
    const float* Wc       = (const float*)d_in[6];
    const float* gamma1   = (const float*)d_in[7];
    const float* beta1    = (const float*)d_in[8];
    const float* alpha1   = (const float*)d_in[9];
    const float* gamma2   = (const float*)d_in[10];
    const float* beta2    = (const float*)d_in[11];
    const float* alpha2   = (const float*)d_in[12];
    float* out = (float*)d_out;

    const int smem1 = 128 * 128 * 4;               // 65536
    const int smem2 = 2 * 128 * (HID + 8) * 2;     // 69632
    cudaFuncSetAttribute(k_gemm, cudaFuncAttributeMaxDynamicSharedMemorySize, smem2);

    k_zero<<<N_NODES / 256, 256>>>();
    k_build<<<E_EDGES / 2048, 256>>>(src, dst, ew);
    k_prep<<<4097, 256>>>(features, W1, W2);

    k_agg1<<<N_NODES / 32, 256>>>();
    k_gemm<<<N_NODES / 128, 256, smem1>>>(1);
    k_norm<<<2048, 128>>>(1, gamma1, beta1, alpha1);

    k_agg2<<<N_NODES / 32, 256>>>();
    k_gemm<<<N_NODES / 128, 256, smem2>>>(2);
    k_norm<<<2048, 128>>>(2, gamma2, beta2, alpha2);

    k_final<<<1, 512>>>(Wc, out);
}